// round 16
// baseline (speedup 1.0000x reference)
#include <cuda_runtime.h>
#include <cuda_bf16.h>
#include <math.h>
#include <stdint.h>

#define NBL 20
#define DD  256
#define NN  1024
#define TM  32           // query rows per CTA
#define TK  128          // kv rows per tile
#define NT  (NN/TK)      // 8
#define THREADS 256
#define LOGTHR 16.118096f   // ln(1e7)

// Precomputed bf16 split of x: hi = bf16(x), lo = bf16(x - hi). 10.5 MB each.
#define XU4 (NBL*DD*NN/8)
__device__ uint4 g_xhi[XU4];
__device__ uint4 g_xlo[XU4];

// ---- smem layout (bytes); strides rotate 16B granules mod 128B (ldmatrix conflict-free)
#define SM_ALPHA 0                     // 32 fp32
#define SM_INVL  128                   // 32 fp32
#define SM_MX    256                   // [32][4] per-Ngroup row maxes
#define SM_SX    768                   // [32][4] per-Ngroup row sums
#define SM_Q     1280                  // bf16 [256 d][40] (32 used), stride 80B
#define QSTRIDE  80
#define SM_KV    (SM_Q + 256*QSTRIDE)  // bf16 [256 d][136] (128 used), stride 272B
#define KVSTRIDE 272
#define SM_P     (SM_KV + 256*KVSTRIDE)// bf16 [32 i][136] (128 used), stride 272B
#define PSTRIDE  272
#define SM_TOTAL (SM_P + 32*PSTRIDE)   // 100096 B  (x2 CTAs = 200 KB <= 227 KB)

__device__ __forceinline__ uint32_t smem_u32(const void* p) {
    uint32_t a;
    asm("{ .reg .u64 t; cvta.to.shared.u64 t, %1; cvt.u32.u64 %0, t; }" : "=r"(a) : "l"(p));
    return a;
}
__device__ __forceinline__ void ldsm4(uint32_t* r, uint32_t a) {
    asm volatile("ldmatrix.sync.aligned.m8n8.x4.shared.b16 {%0,%1,%2,%3}, [%4];"
                 : "=r"(r[0]), "=r"(r[1]), "=r"(r[2]), "=r"(r[3]) : "r"(a));
}
__device__ __forceinline__ void ldsm4t(uint32_t* r, uint32_t a) {
    asm volatile("ldmatrix.sync.aligned.m8n8.x4.trans.shared.b16 {%0,%1,%2,%3}, [%4];"
                 : "=r"(r[0]), "=r"(r[1]), "=r"(r[2]), "=r"(r[3]) : "r"(a));
}
__device__ __forceinline__ void mma16816(float* d, const uint32_t* a, uint32_t b0, uint32_t b1) {
    asm volatile("mma.sync.aligned.m16n8k16.row.col.f32.bf16.bf16.f32 "
                 "{%0,%1,%2,%3},{%4,%5,%6,%7},{%8,%9},{%0,%1,%2,%3};"
                 : "+f"(d[0]), "+f"(d[1]), "+f"(d[2]), "+f"(d[3])
                 : "r"(a[0]), "r"(a[1]), "r"(a[2]), "r"(a[3]), "r"(b0), "r"(b1));
}
__device__ __forceinline__ void cp_async16(uint32_t saddr, const void* gaddr) {
    asm volatile("cp.async.cg.shared.global [%0], [%1], 16;" :: "r"(saddr), "l"(gaddr) : "memory");
}
#define CP_COMMIT() asm volatile("cp.async.commit_group;" ::: "memory")
#define CP_WAIT0()  asm volatile("cp.async.wait_group 0;" ::: "memory")

// ---- kernel 1: split x into bf16 hi/lo ----
__global__ void __launch_bounds__(512, 2)
split_bf16(const float* __restrict__ x)
{
    int i0 = (blockIdx.x * 512 + threadIdx.x) * 4;
#pragma unroll
    for (int it = 0; it < 4; ++it) {
        int i = i0 + it;
        float4 v = *((const float4*)x + i);
        __nv_bfloat162 h0 = __floats2bfloat162_rn(v.x, v.y);
        __nv_bfloat162 h1 = __floats2bfloat162_rn(v.z, v.w);
        __nv_bfloat162 l0 = __floats2bfloat162_rn(v.x - __bfloat162float(h0.x),
                                                  v.y - __bfloat162float(h0.y));
        __nv_bfloat162 l1 = __floats2bfloat162_rn(v.z - __bfloat162float(h1.x),
                                                  v.w - __bfloat162float(h1.y));
        ((uint2*)g_xhi)[i] = make_uint2(*(uint32_t*)&h0, *(uint32_t*)&h1);
        ((uint2*)g_xlo)[i] = make_uint2(*(uint32_t*)&l0, *(uint32_t*)&l1);
    }
}

__global__ void __launch_bounds__(THREADS, 2)
attn_hmma(const int* __restrict__ beta_p, float* __restrict__ out)
{
    extern __shared__ char smem[];
    const uint32_t sb = smem_u32(smem);
    const int t = threadIdx.x, lane = t & 31, wid = t >> 5;
    const int mt = blockIdx.x;            // 0..31 row-tile of 32
    const int n0 = mt * TM;
    const int bl = blockIdx.y;
    float* __restrict__ ob = out + (size_t)bl * NN * DD;

    float betaf = 1.0f;
    if (beta_p) {
        int bbits = *beta_p;
        float bf = __int_as_float(bbits);
        betaf = (fabsf(bf) >= 1e-6f && fabsf(bf) <= 1e6f) ? bf : (float)bbits;
    }

    float* Alpha = (float*)(smem + SM_ALPHA);
    float* Invl  = (float*)(smem + SM_INVL);
    float* Mx    = (float*)(smem + SM_MX);
    float* Sx    = (float*)(smem + SM_SX);

    const size_t eb = (size_t)bl * DD * NN;
    const int ld_d = t >> 4, ld_j = t & 15;   // KV copy slice (16 uint4 per d-row)

    const int dt = mt >> 2;                   // diagonal tile (cols [n0,n0+32) live in tile mt/4)

    // ---- prefetch diagonal tile into KV via cp.async ----
    {
        const int j0g = dt * TK;
#pragma unroll
        for (int it = 0; it < 16; ++it) {
            int d = ld_d + it * 16;
            cp_async16(sb + SM_KV + d * KVSTRIDE + ld_j * 16,
                       &g_xhi[(eb + (size_t)d * NN + j0g) / 8 + ld_j]);
        }
        CP_COMMIT();
    }

    // ---- Q: bf16 [d][n0..n0+31] -> smem [d][i] (1024 uint4) ----
#pragma unroll
    for (int it = 0; it < 4; ++it) {
        int idx = it * THREADS + t;
        int d = idx >> 2, ic = idx & 3;
        uint4 w = g_xhi[(eb + (size_t)d * NN + n0) / 8 + ic];
        *(uint4*)(smem + SM_Q + d * QSTRIDE + ic * 16) = w;
    }

    // GEMM2 accumulators: warp owns 32 d-cols [db,db+32)
    float acc2[2][4][4];
#pragma unroll
    for (int a = 0; a < 2; ++a)
#pragma unroll
        for (int b = 0; b < 4; ++b)
#pragma unroll
            for (int c = 0; c < 4; ++c) acc2[a][b][c] = 0.f;

    const int mw = wid & 1, nw = wid >> 1;    // GEMM1: 2 M x 4 N warp grid
    const int i0 = mw * 16, jb = nw * 32;
    const int db = wid * 32;                  // GEMM2: warp owns 32 d-cols
    const int r0 = i0 + (lane >> 2), r1 = r0 + 8;

    const uint32_t qa = sb + SM_Q + (uint32_t)((lane & 7) + ((lane >> 1) & 8)) * QSTRIDE
                      + (uint32_t)(i0 + (lane & 8)) * 2;
    const uint32_t kb0 = sb + SM_KV + (uint32_t)((lane & 7) + (lane & 8)) * KVSTRIDE
                       + (uint32_t)(jb + ((lane >> 1) & 8)) * 2;

    float m0 = -1e30f, m1 = -1e30f;
    float l0 = 0.f, l1 = 0.f;

    for (int idx8 = 0; idx8 < NT; ++idx8) {
        const int kt = (idx8 == 0) ? dt : (idx8 <= dt ? idx8 - 1 : idx8);
        const int j0g = kt * TK;

        // ---- load tile (idx8>0): prior iteration ended at a barrier, KV free ----
        if (idx8 > 0) {
#pragma unroll
            for (int it = 0; it < 16; ++it) {
                int d = ld_d + it * 16;
                cp_async16(sb + SM_KV + d * KVSTRIDE + ld_j * 16,
                           &g_xhi[(eb + (size_t)d * NN + j0g) / 8 + ld_j]);
            }
            CP_COMMIT();
        }
        CP_WAIT0();
        __syncthreads();

        // ---- GEMM1: S[32][128] = Q @ K^T; warp tile 16 x 32 (regs only) ----
        float acc1[4][4];
#pragma unroll
        for (int n = 0; n < 4; ++n)
#pragma unroll
            for (int c = 0; c < 4; ++c) acc1[n][c] = 0.f;
#pragma unroll
        for (int k = 0; k < 16; ++k) {
            const uint32_t dof = (uint32_t)(k * 16);
            uint32_t afr[4];
            ldsm4t(afr, qa + dof * QSTRIDE);
#pragma unroll
            for (int h = 0; h < 2; ++h) {
                uint32_t bfr[4];
                ldsm4t(bfr, kb0 + dof * KVSTRIDE + (uint32_t)(h * 16) * 2);
                mma16816(acc1[2 * h],     afr, bfr[0], bfr[1]);
                mma16816(acc1[2 * h + 1], afr, bfr[2], bfr[3]);
            }
        }

        // ---- warp-partial row maxes of beta*S ----
        float wm0 = -1e30f, wm1 = -1e30f;
#pragma unroll
        for (int n = 0; n < 4; ++n) {
            wm0 = fmaxf(wm0, fmaxf(betaf * acc1[n][0], betaf * acc1[n][1]));
            wm1 = fmaxf(wm1, fmaxf(betaf * acc1[n][2], betaf * acc1[n][3]));
        }
        wm0 = fmaxf(wm0, __shfl_xor_sync(0xffffffffu, wm0, 1));
        wm0 = fmaxf(wm0, __shfl_xor_sync(0xffffffffu, wm0, 2));
        wm1 = fmaxf(wm1, __shfl_xor_sync(0xffffffffu, wm1, 1));
        wm1 = fmaxf(wm1, __shfl_xor_sync(0xffffffffu, wm1, 2));

        int need = __syncthreads_or((wm0 > m0 - LOGTHR) || (wm1 > m1 - LOGTHR));
        if (!need) continue;   // tile certified negligible (all p < 1e-7)

        // ---- executed tile: cross-warp max ----
        if ((lane & 3) == 0) { Mx[r0 * 4 + nw] = wm0; Mx[r1 * 4 + nw] = wm1; }
        __syncthreads();
        float4 q0 = *(const float4*)(Mx + r0 * 4);
        float4 q1 = *(const float4*)(Mx + r1 * 4);
        float t0 = fmaxf(fmaxf(q0.x, q0.y), fmaxf(q0.z, q0.w));
        float t1 = fmaxf(fmaxf(q1.x, q1.y), fmaxf(q1.z, q1.w));
        float n_m0 = fmaxf(m0, t0), n_m1 = fmaxf(m1, t1);
        float al0 = __expf(m0 - n_m0), al1 = __expf(m1 - n_m1);

        float ws0 = 0.f, ws1 = 0.f;
#pragma unroll
        for (int n = 0; n < 4; ++n) {
            float p00 = __expf(betaf * acc1[n][0] - n_m0);
            float p01 = __expf(betaf * acc1[n][1] - n_m0);
            float p10 = __expf(betaf * acc1[n][2] - n_m1);
            float p11 = __expf(betaf * acc1[n][3] - n_m1);
            ws0 += p00 + p01; ws1 += p10 + p11;
            __nv_bfloat162 v0 = __floats2bfloat162_rn(p00, p01);
            __nv_bfloat162 v1 = __floats2bfloat162_rn(p10, p11);
            int col = jb + n * 8 + 2 * (lane & 3);
            *(uint32_t*)(smem + SM_P + r0 * PSTRIDE + col * 2) = *(uint32_t*)&v0;
            *(uint32_t*)(smem + SM_P + r1 * PSTRIDE + col * 2) = *(uint32_t*)&v1;
        }
        ws0 += __shfl_xor_sync(0xffffffffu, ws0, 1);
        ws0 += __shfl_xor_sync(0xffffffffu, ws0, 2);
        ws1 += __shfl_xor_sync(0xffffffffu, ws1, 1);
        ws1 += __shfl_xor_sync(0xffffffffu, ws1, 2);
        if ((lane & 3) == 0) {
            Sx[r0 * 4 + nw] = ws0; Sx[r1 * 4 + nw] = ws1;
            if (nw == 0) { Alpha[r0] = al0; Alpha[r1] = al1; }
        }
        __syncthreads();   // P, Sx, Alpha visible

        float4 s0 = *(const float4*)(Sx + r0 * 4);
        float4 s1 = *(const float4*)(Sx + r1 * 4);
        l0 = l0 * al0 + (s0.x + s0.y) + (s0.z + s0.w);
        l1 = l1 * al1 + (s1.x + s1.y) + (s1.z + s1.w);
        m0 = n_m0; m1 = n_m1;

        if (idx8 > 0) {
#pragma unroll
            for (int mtt = 0; mtt < 2; ++mtt) {
                float a0 = Alpha[16 * mtt + (lane >> 2)];
                float a1 = Alpha[16 * mtt + (lane >> 2) + 8];
#pragma unroll
                for (int h = 0; h < 4; ++h) {
                    acc2[mtt][h][0] *= a0; acc2[mtt][h][1] *= a0;
                    acc2[mtt][h][2] *= a1; acc2[mtt][h][3] *= a1;
                }
            }
        }

        // ---- GEMM2 pass A: O += P @ V_hi ----
        const uint32_t pbs = sb + SM_P;
#pragma unroll
        for (int kk = 0; kk < 8; ++kk) {
            const int j0 = kk * 16;
            uint32_t ap[2][4];
#pragma unroll
            for (int mtt = 0; mtt < 2; ++mtt)
                ldsm4(ap[mtt], pbs + (uint32_t)(16 * mtt + (lane & 7) + (lane & 8)) * PSTRIDE
                                   + (uint32_t)(j0 + ((lane >> 1) & 8)) * 2);
            uint32_t bh[2][4];
#pragma unroll
            for (int h = 0; h < 2; ++h)
                ldsm4(bh[h], sb + SM_KV
                             + (uint32_t)(db + h * 16 + (lane & 7) + ((lane >> 1) & 8)) * KVSTRIDE
                             + (uint32_t)(j0 + (lane & 8)) * 2);
#pragma unroll
            for (int mtt = 0; mtt < 2; ++mtt)
#pragma unroll
                for (int h = 0; h < 2; ++h) {
                    mma16816(acc2[mtt][2 * h],     ap[mtt], bh[h][0], bh[h][1]);
                    mma16816(acc2[mtt][2 * h + 1], ap[mtt], bh[h][2], bh[h][3]);
                }
        }
        __syncthreads();   // pass-A reads of KV done before overwrite

        // ---- overwrite KV with V_lo (plain loads; ~once per CTA) ----
#pragma unroll
        for (int it = 0; it < 16; ++it) {
            int d = ld_d + it * 16;
            uint4 w = g_xlo[(eb + (size_t)d * NN + j0g) / 8 + ld_j];
            *(uint4*)(smem + SM_KV + d * KVSTRIDE + ld_j * 16) = w;
        }
        __syncthreads();

        // ---- GEMM2 pass B: O += P @ V_lo ----
#pragma unroll
        for (int kk = 0; kk < 8; ++kk) {
            const int j0 = kk * 16;
            uint32_t ap[2][4];
#pragma unroll
            for (int mtt = 0; mtt < 2; ++mtt)
                ldsm4(ap[mtt], pbs + (uint32_t)(16 * mtt + (lane & 7) + (lane & 8)) * PSTRIDE
                                   + (uint32_t)(j0 + ((lane >> 1) & 8)) * 2);
            uint32_t bl2[2][4];
#pragma unroll
            for (int h = 0; h < 2; ++h)
                ldsm4(bl2[h], sb + SM_KV
                              + (uint32_t)(db + h * 16 + (lane & 7) + ((lane >> 1) & 8)) * KVSTRIDE
                              + (uint32_t)(j0 + (lane & 8)) * 2);
#pragma unroll
            for (int mtt = 0; mtt < 2; ++mtt)
#pragma unroll
                for (int h = 0; h < 2; ++h) {
                    mma16816(acc2[mtt][2 * h],     ap[mtt], bl2[h][0], bl2[h][1]);
                    mma16816(acc2[mtt][2 * h + 1], ap[mtt], bl2[h][2], bl2[h][3]);
                }
        }
        __syncthreads();   // pass-B reads done before next tile's cp.async overwrite
    }

    // ---- epilogue: publish 1/l, normalize, store ----
    if (nw == 0 && (lane & 3) == 0) { Invl[r0] = 1.f / l0; Invl[r1] = 1.f / l1; }
    __syncthreads();
#pragma unroll
    for (int mtt = 0; mtt < 2; ++mtt) {
        const int rr = 16 * mtt + (lane >> 2);
        const float w0 = Invl[rr];
        const float w1 = Invl[rr + 8];
#pragma unroll
        for (int h = 0; h < 4; ++h) {
            const int col = db + 8 * h + 2 * (lane & 3);
            float2 v0 = make_float2(acc2[mtt][h][0] * w0, acc2[mtt][h][1] * w0);
            float2 v1 = make_float2(acc2[mtt][h][2] * w1, acc2[mtt][h][3] * w1);
            *(float2*)(ob + (size_t)(n0 + rr) * DD + col) = v0;
            *(float2*)(ob + (size_t)(n0 + rr + 8) * DD + col) = v1;
        }
    }
}

extern "C" void kernel_launch(void* const* d_in, const int* in_sizes, int n_in,
                              void* d_out, int out_size)
{
    const float* x = (const float*)d_in[0];
    const int* beta = (n_in > 1) ? (const int*)d_in[1] : nullptr;
    float* out = (float*)d_out;

    split_bf16<<<XU4 / (512 * 2), 512>>>(x);

    cudaFuncSetAttribute(attn_hmma, cudaFuncAttributeMaxDynamicSharedMemorySize, SM_TOTAL);
    dim3 grid(NN / TM, NBL);   // 32 x 20 = 640 CTAs
    attn_hmma<<<grid, THREADS, SM_TOTAL>>>(beta, out);
}